// round 1
// baseline (speedup 1.0000x reference)
#include <cuda_runtime.h>
#include <math.h>

#define NB 16
#define NS 512
#define NH 16
#define ND 64
#define NHID 1024
#define NROW (NB*NS)        // 8192
#define NBH (NB*NH)         // 256
#define NTOK (NBH*NS*ND)    // 8388608

// ---------------- scratch (static __device__, allocation-guard safe) ----------------
__device__ __align__(16) float g_proj[2][NROW*NHID];   // raw projections (img, txt)
__device__ __align__(16) float g_c[2][NTOK];           // 0: ci, 1: ct  (B,H,S,D)
__device__ __align__(16) float g_q[2][NTOK];
__device__ __align__(16) float g_k[2][NTOK];
__device__ __align__(16) float g_v[2][NTOK];
__device__ __align__(16) float g_o[2][NTOK];
__device__ __align__(16) float g_comb[NBH*NS*2*ND];    // (B,H,S,128)

// ---------------- big projection GEMM: C[M,1024] = A[M,K] @ W[1024,K]^T + bias ------
__global__ void gemm_bias_kernel(const float* __restrict__ A,
                                 const float* __restrict__ W,
                                 const float* __restrict__ bias,
                                 int K, int which) {
    __shared__ __align__(16) float As[16][64];
    __shared__ __align__(16) float Ws[16][64];
    float* C = g_proj[which];
    const int N = NHID;
    int tid = threadIdx.x;
    int tx = tid & 15, ty = tid >> 4;
    int m0 = blockIdx.y * 64, n0 = blockIdx.x * 64;
    int lrow = tid >> 2;
    int lk = (tid & 3) * 4;
    float acc[4][4] = {};
    for (int k0 = 0; k0 < K; k0 += 16) {
        float4 av = *(const float4*)(A + (size_t)(m0 + lrow) * K + k0 + lk);
        float4 wv = *(const float4*)(W + (size_t)(n0 + lrow) * K + k0 + lk);
        As[lk+0][lrow]=av.x; As[lk+1][lrow]=av.y; As[lk+2][lrow]=av.z; As[lk+3][lrow]=av.w;
        Ws[lk+0][lrow]=wv.x; Ws[lk+1][lrow]=wv.y; Ws[lk+2][lrow]=wv.z; Ws[lk+3][lrow]=wv.w;
        __syncthreads();
        #pragma unroll
        for (int kk = 0; kk < 16; kk++) {
            float4 a4 = *(const float4*)(&As[kk][ty*4]);
            float4 w4 = *(const float4*)(&Ws[kk][tx*4]);
            float a[4] = {a4.x, a4.y, a4.z, a4.w};
            float w[4] = {w4.x, w4.y, w4.z, w4.w};
            #pragma unroll
            for (int i=0;i<4;i++)
                #pragma unroll
                for (int j=0;j<4;j++) acc[i][j] = fmaf(a[i], w[j], acc[i][j]);
        }
        __syncthreads();
    }
    #pragma unroll
    for (int i=0;i<4;i++) {
        int m = m0 + ty*4 + i;
        #pragma unroll
        for (int j=0;j<4;j++) {
            int n = n0 + tx*4 + j;
            C[(size_t)m*N + n] = acc[i][j] + bias[n];
        }
    }
}

// ---------------- LN + l2-normalize + D^-0.5, writes (B,H,S,D) layout ----------------
__device__ __forceinline__ float breduce256(float v, float* red) {
    #pragma unroll
    for (int o = 16; o > 0; o >>= 1) v += __shfl_xor_sync(0xffffffffu, v, o);
    int tid = threadIdx.x;
    if ((tid & 31) == 0) red[tid >> 5] = v;
    __syncthreads();
    float t = 0.f;
    #pragma unroll
    for (int i = 0; i < 8; i++) t += red[i];
    __syncthreads();
    return t;
}

__global__ void ln_l2_kernel(const float* __restrict__ g, const float* __restrict__ b, int which) {
    __shared__ float red[8];
    int row = blockIdx.x;              // 0..8191 : b*512+s
    int tid = threadIdx.x;
    const float* y = g_proj[which] + (size_t)row * NHID;
    float v[4], sum = 0.f;
    #pragma unroll
    for (int i=0;i<4;i++){ v[i] = y[tid + i*256]; sum += v[i]; }
    sum = breduce256(sum, red);
    float mu = sum * (1.f/NHID);
    float sq = 0.f;
    #pragma unroll
    for (int i=0;i<4;i++){ float d = v[i]-mu; sq += d*d; }
    sq = breduce256(sq, red);
    float rstd = rsqrtf(sq*(1.f/NHID) + 1e-5f);
    float ln[4], s2 = 0.f;
    #pragma unroll
    for (int i=0;i<4;i++){ int n = tid+i*256; ln[i] = (v[i]-mu)*rstd*g[n] + b[n]; s2 += ln[i]*ln[i]; }
    s2 = breduce256(s2, red);
    float scale = 0.125f / fmaxf(sqrtf(s2), 1e-12f);   // l2 norm * D^-0.5
    int bb = row >> 9, s = row & 511;
    float* outp = g_c[which];
    #pragma unroll
    for (int i=0;i<4;i++){
        int n = tid + i*256;
        int h = n >> 6, d = n & 63;
        outp[(((size_t)(bb*NH + h))*NS + s)*ND + d] = ln[i]*scale;
    }
}

// ---------------- per-head QKV projection: [64 rows] x [64x64 W] -------------------
__global__ void qkv_kernel(const float* __restrict__ in_w, const float* __restrict__ in_b, int which) {
    __shared__ __align__(16) float Xq[64][64];    // [d][s]
    __shared__ __align__(16) float Xkv[64][64];   // [d][s]
    __shared__ __align__(16) float Ws[64][64];    // [d][e]
    const float* qsrc  = g_c[which];
    const float* kvsrc = g_c[which ^ 1];
    int bh = blockIdx.y;
    int h = bh & (NH-1);
    int s0 = blockIdx.x * 64;
    int tid = threadIdx.x, tx = tid & 15, ty = tid >> 4;
    int lrow = tid >> 2;
    const float* qbase  = qsrc  + ((size_t)bh*NS + s0)*ND;
    const float* kvbase = kvsrc + ((size_t)bh*NS + s0)*ND;
    #pragma unroll
    for (int it = 0; it < 4; it++) {
        int c = ((tid & 3) + it*4) * 4;
        float4 a  = *(const float4*)(qbase  + lrow*64 + c);
        float4 kv = *(const float4*)(kvbase + lrow*64 + c);
        Xq[c+0][lrow]=a.x;  Xq[c+1][lrow]=a.y;  Xq[c+2][lrow]=a.z;  Xq[c+3][lrow]=a.w;
        Xkv[c+0][lrow]=kv.x;Xkv[c+1][lrow]=kv.y;Xkv[c+2][lrow]=kv.z;Xkv[c+3][lrow]=kv.w;
    }
    for (int p = 0; p < 3; p++) {
        const float* wsrc = in_w + ((size_t)h*192 + p*64)*64;   // W[e][d]
        #pragma unroll
        for (int it = 0; it < 4; it++) {
            int c = ((tid & 3) + it*4) * 4;
            float4 w = *(const float4*)(wsrc + lrow*64 + c);
            Ws[c+0][lrow]=w.x; Ws[c+1][lrow]=w.y; Ws[c+2][lrow]=w.z; Ws[c+3][lrow]=w.w;
        }
        __syncthreads();
        const float (*X)[64] = (p == 0) ? Xq : Xkv;
        float acc[4][4] = {};
        #pragma unroll 8
        for (int d = 0; d < 64; d++) {
            float4 a4 = *(const float4*)(&X[d][ty*4]);
            float4 w4 = *(const float4*)(&Ws[d][tx*4]);
            float a[4] = {a4.x, a4.y, a4.z, a4.w};
            float w[4] = {w4.x, w4.y, w4.z, w4.w};
            #pragma unroll
            for (int i=0;i<4;i++)
                #pragma unroll
                for (int j=0;j<4;j++) acc[i][j] = fmaf(a[i], w[j], acc[i][j]);
        }
        float* dst = (p==0) ? g_q[which] : (p==1) ? g_k[which] : g_v[which];
        float qscale = (p==0) ? 0.125f : 1.f;     // extra D^-0.5 on q
        #pragma unroll
        for (int i=0;i<4;i++){
            int s = s0 + ty*4 + i;
            #pragma unroll
            for (int j=0;j<4;j++){
                int e = tx*4 + j;
                dst[((size_t)bh*NS + s)*ND + e] = (acc[i][j] + in_b[h*192 + p*64 + e]) * qscale;
            }
        }
        __syncthreads();
    }
}

// ---------------- flash-style attention, 64-query tile, full 512 KV sweep ----------
__global__ void attn_kernel(int which) {
    extern __shared__ __align__(16) float sm[];
    float (*qs)[64] = (float(*)[64])sm;              // [d][i]
    float (*ks)[64] = (float(*)[64])(sm + 4096);     // [d][j]
    float (*vs)[64] = (float(*)[64])(sm + 8192);     // [j][e]
    float (*ps)[65] = (float(*)[65])(sm + 12288);    // [i][j] padded
    float* rowm = sm + 12288 + 4160;
    float* rowl = rowm + 64;
    float* rowf = rowl + 64;
    const float* Q = g_q[which];
    const float* K = g_k[which];
    const float* V = g_v[which];
    float* O = g_o[which];
    int bh = blockIdx.y, q0 = blockIdx.x * 64;
    int tid = threadIdx.x, tx = tid & 15, ty = tid >> 4;
    int lrow = tid >> 2;
    const float* qbase = Q + ((size_t)bh*NS + q0)*ND;
    #pragma unroll
    for (int it = 0; it < 4; it++) {
        int c = ((tid & 3) + it*4) * 4;
        float4 a = *(const float4*)(qbase + lrow*64 + c);
        qs[c+0][lrow]=a.x; qs[c+1][lrow]=a.y; qs[c+2][lrow]=a.z; qs[c+3][lrow]=a.w;
    }
    if (tid < 64) { rowm[tid] = -1e30f; rowl[tid] = 0.f; }
    float o[4][4] = {};
    __syncthreads();
    for (int j0 = 0; j0 < NS; j0 += 64) {
        const float* kbase = K + ((size_t)bh*NS + j0)*ND;
        const float* vbase = V + ((size_t)bh*NS + j0)*ND;
        #pragma unroll
        for (int it = 0; it < 4; it++) {
            int c = ((tid & 3) + it*4) * 4;
            float4 kk = *(const float4*)(kbase + lrow*64 + c);
            ks[c+0][lrow]=kk.x; ks[c+1][lrow]=kk.y; ks[c+2][lrow]=kk.z; ks[c+3][lrow]=kk.w;
            ((float4*)vs)[tid + it*256] = ((const float4*)vbase)[tid + it*256];
        }
        __syncthreads();
        float sc[4][4] = {};
        #pragma unroll 8
        for (int d = 0; d < 64; d++) {
            float4 a4 = *(const float4*)(&qs[d][ty*4]);
            float4 k4 = *(const float4*)(&ks[d][tx*4]);
            float a[4] = {a4.x, a4.y, a4.z, a4.w};
            float k[4] = {k4.x, k4.y, k4.z, k4.w};
            #pragma unroll
            for (int i=0;i<4;i++)
                #pragma unroll
                for (int j=0;j<4;j++) sc[i][j] = fmaf(a[i], k[j], sc[i][j]);
        }
        #pragma unroll
        for (int i=0;i<4;i++)
            #pragma unroll
            for (int j=0;j<4;j++) ps[ty*4+i][tx*4+j] = sc[i][j];
        __syncthreads();
        if (tid < 64) {
            float mold = rowm[tid];
            float mx = mold;
            #pragma unroll 8
            for (int j=0;j<64;j++) mx = fmaxf(mx, ps[tid][j]);
            float f = __expf(mold - mx);
            float l = 0.f;
            #pragma unroll 8
            for (int j=0;j<64;j++){ float e = __expf(ps[tid][j] - mx); ps[tid][j] = e; l += e; }
            rowl[tid] = rowl[tid]*f + l;
            rowm[tid] = mx;
            rowf[tid] = f;
        }
        __syncthreads();
        float fi[4];
        #pragma unroll
        for (int i=0;i<4;i++) fi[i] = rowf[ty*4+i];
        #pragma unroll
        for (int i=0;i<4;i++)
            #pragma unroll
            for (int j=0;j<4;j++) o[i][j] *= fi[i];
        #pragma unroll 8
        for (int j=0;j<64;j++){
            float p4[4];
            #pragma unroll
            for (int i=0;i<4;i++) p4[i] = ps[ty*4+i][j];
            float4 v4 = *(const float4*)(&vs[j][tx*4]);
            float vv[4] = {v4.x, v4.y, v4.z, v4.w};
            #pragma unroll
            for (int i=0;i<4;i++)
                #pragma unroll
                for (int e=0;e<4;e++) o[i][e] = fmaf(p4[i], vv[e], o[i][e]);
        }
        __syncthreads();
    }
    float il[4];
    #pragma unroll
    for (int i=0;i<4;i++) il[i] = 1.f / rowl[ty*4+i];
    #pragma unroll
    for (int i=0;i<4;i++)
        #pragma unroll
        for (int e=0;e<4;e++)
            O[((size_t)bh*NS + q0 + ty*4+i)*ND + tx*4+e] = o[i][e] * il[i];
}

// ---------------- out projection + residual, writes concat halves -----------------
__global__ void outproj_kernel(const float* __restrict__ out_w, const float* __restrict__ out_b, int which) {
    __shared__ __align__(16) float Xs[64][64];   // [e][s]
    __shared__ __align__(16) float Ws[64][64];   // [e][f]
    const float* Oin   = g_o[which];
    const float* resid = g_c[which];
    int bh = blockIdx.y, h = bh & (NH-1), s0 = blockIdx.x*64;
    int tid = threadIdx.x, tx = tid&15, ty = tid>>4, lrow = tid>>2;
    const float* xbase = Oin + ((size_t)bh*NS + s0)*ND;
    const float* wsrc  = out_w + (size_t)h*64*64;       // W[f][e]
    #pragma unroll
    for (int it=0; it<4; it++){
        int c = ((tid&3)+it*4)*4;
        float4 x = *(const float4*)(xbase + lrow*64 + c);
        float4 w = *(const float4*)(wsrc  + lrow*64 + c);
        Xs[c+0][lrow]=x.x; Xs[c+1][lrow]=x.y; Xs[c+2][lrow]=x.z; Xs[c+3][lrow]=x.w;
        Ws[c+0][lrow]=w.x; Ws[c+1][lrow]=w.y; Ws[c+2][lrow]=w.z; Ws[c+3][lrow]=w.w;
    }
    __syncthreads();
    float acc[4][4] = {};
    #pragma unroll 8
    for (int e = 0; e < 64; e++) {
        float4 a4 = *(const float4*)(&Xs[e][ty*4]);
        float4 w4 = *(const float4*)(&Ws[e][tx*4]);
        float a[4] = {a4.x, a4.y, a4.z, a4.w};
        float w[4] = {w4.x, w4.y, w4.z, w4.w};
        #pragma unroll
        for (int i=0;i<4;i++)
            #pragma unroll
            for (int j=0;j<4;j++) acc[i][j] = fmaf(a[i], w[j], acc[i][j]);
    }
    int off = which * 64;
    #pragma unroll
    for (int i=0;i<4;i++){
        int s = s0 + ty*4 + i;
        #pragma unroll
        for (int j=0;j<4;j++){
            int f = tx*4 + j;
            g_comb[((size_t)bh*NS + s)*128 + off + f] =
                acc[i][j] + out_b[h*64+f] + resid[((size_t)bh*NS+s)*ND + f];
        }
    }
}

// ---------------- final LN over concat dim (128), one warp per row ----------------
__global__ void final_ln_kernel(const float* __restrict__ hg, const float* __restrict__ hb,
                                float* __restrict__ out) {
    int row = blockIdx.x * 8 + (threadIdx.x >> 5);   // 0..131071 = (b*16+h)*512+s
    int lane = threadIdx.x & 31;
    const float* x = g_comb + (size_t)row * 128;
    float v[4], sum = 0.f;
    #pragma unroll
    for (int i=0;i<4;i++){ v[i] = x[lane + i*32]; sum += v[i]; }
    #pragma unroll
    for (int o = 16; o > 0; o >>= 1) sum += __shfl_xor_sync(0xffffffffu, sum, o);
    float mu = sum * (1.f/128.f);
    float sq = 0.f;
    #pragma unroll
    for (int i=0;i<4;i++){ float d = v[i]-mu; sq += d*d; }
    #pragma unroll
    for (int o = 16; o > 0; o >>= 1) sq += __shfl_xor_sync(0xffffffffu, sq, o);
    float rstd = rsqrtf(sq*(1.f/128.f) + 1e-5f);
    int h = (row >> 9) & 15;
    #pragma unroll
    for (int i=0;i<4;i++){
        int c = lane + i*32;
        out[(size_t)row*128 + c] = (v[i]-mu)*rstd*hg[h*128+c] + hb[h*128+c];
    }
}

// ---------------- launch ----------------
extern "C" void kernel_launch(void* const* d_in, const int* in_sizes, int n_in,
                              void* d_out, int out_size) {
    const float* image     = (const float*)d_in[0];
    const float* text      = (const float*)d_in[1];
    const float* img_w     = (const float*)d_in[2];
    const float* img_b     = (const float*)d_in[3];
    const float* img_g     = (const float*)d_in[4];
    const float* img_lb    = (const float*)d_in[5];
    const float* txt_w     = (const float*)d_in[6];
    const float* txt_b     = (const float*)d_in[7];
    const float* txt_g     = (const float*)d_in[8];
    const float* txt_lb    = (const float*)d_in[9];
    const float* i2t_in_w  = (const float*)d_in[10];
    const float* i2t_in_b  = (const float*)d_in[11];
    const float* i2t_out_w = (const float*)d_in[12];
    const float* i2t_out_b = (const float*)d_in[13];
    const float* t2i_in_w  = (const float*)d_in[14];
    const float* t2i_in_b  = (const float*)d_in[15];
    const float* t2i_out_w = (const float*)d_in[16];
    const float* t2i_out_b = (const float*)d_in[17];
    const float* hn_g      = (const float*)d_in[18];
    const float* hn_b      = (const float*)d_in[19];
    float* out = (float*)d_out;

    cudaFuncSetAttribute(attn_kernel, cudaFuncAttributeMaxDynamicSharedMemorySize, 66560);

    dim3 thr(256);
    gemm_bias_kernel<<<dim3(16,128), thr>>>(image, img_w, img_b, 768, 0);
    gemm_bias_kernel<<<dim3(16,128), thr>>>(text,  txt_w, txt_b, 512, 1);
    ln_l2_kernel<<<8192, thr>>>(img_g, img_lb, 0);
    ln_l2_kernel<<<8192, thr>>>(txt_g, txt_lb, 1);
    qkv_kernel<<<dim3(8,256), thr>>>(i2t_in_w, i2t_in_b, 0);
    qkv_kernel<<<dim3(8,256), thr>>>(t2i_in_w, t2i_in_b, 1);
    attn_kernel<<<dim3(8,256), thr, 66560>>>(0);
    attn_kernel<<<dim3(8,256), thr, 66560>>>(1);
    outproj_kernel<<<dim3(8,256), thr>>>(i2t_out_w, i2t_out_b, 0);
    outproj_kernel<<<dim3(8,256), thr>>>(t2i_out_w, t2i_out_b, 1);
    final_ln_kernel<<<16384, thr>>>(hn_g, hn_b, out);
}